// round 14
// baseline (speedup 1.0000x reference)
#include <cuda_runtime.h>
#include <math.h>

// Shapes (fixed by the problem)
#define Bc 4
#define Hc 16
#define Sc 1024
#define Dc 64

// Tiling
#define BQ 128
#define BKT 64
#define DPAD 68      // 64 + 4 pad (floats) — float4-aligned rows, breaks bank patterns
#define BKPAD 68
#define NTHREADS 256

// Mask layout flag: 0 = 32-bit words (int32 or float32 bool), 1 = 1-byte bools
__device__ int g_mask_byte_mode;

__global__ void detect_mask_dtype_kernel(const unsigned int* __restrict__ m) {
    __shared__ int bad;
    if (threadIdx.x == 0) bad = 0;
    __syncthreads();
    // int32 bools  -> words in {0,1}
    // float32 bools-> words in {0, 0x3F800000}
    // u8 bools     -> packed words like 0x01010101 appear w.p. 7/8 per word
    int local_bad = 0;
    for (int i = threadIdx.x; i < 8192; i += blockDim.x) {
        unsigned int w = m[i];
        if (w != 0u && w != 1u && w != 0x3F800000u) local_bad = 1;
    }
    if (local_bad) bad = 1;
    __syncthreads();
    if (threadIdx.x == 0) g_mask_byte_mode = bad;
}

// minBlocksPerMultiprocessor=2 caps regs at 128 -> 2 CTAs (16 warps) per SM.
__global__ __launch_bounds__(NTHREADS, 2)
void attn_flash_kernel(const float* __restrict__ Q,
                       const float* __restrict__ K,
                       const float* __restrict__ V,
                       const void* __restrict__ MSK,
                       const float* __restrict__ TW,
                       const float* __restrict__ DU,
                       float* __restrict__ O) {
    extern __shared__ float sm[];
    float* sQ = sm;                          // BQ  x DPAD  (pre-scaled by 1/8)
    float* sK = sQ + BQ * DPAD;              // BKT x DPAD
    float* sV = sK + BKT * DPAD;             // BKT x DPAD
    float* sP = sV + BKT * DPAD;             // BQ  x BKPAD (weights, written once)
    float* sMx = sP + BQ * BKPAD;            // BQ running max
    float* sZ  = sMx + BQ;                   // BQ running denom
    float* sC  = sZ + BQ;                    // BQ correction factor

    const int t  = threadIdx.x;
    const int bh = blockIdx.x >> 3;          // Sc/BQ == 8 q-tiles
    const int q0 = (blockIdx.x & 7) * BQ;

    const int mask_bytes = g_mask_byte_mode; // uniform across grid

    const size_t qkvbase = (size_t)bh * Sc * Dc;
    const size_t mbase   = (size_t)bh * Sc * Sc;
    const float* Qb = Q + qkvbase;
    const float* Kb = K + qkvbase;
    const float* Vb = V + qkvbase;
    const unsigned int*  MbW = (const unsigned int*)MSK + mbase;   // word bools
    const unsigned char* MbB = (const unsigned char*)MSK + mbase;  // byte bools
    const float* Tb = TW + mbase;
    const float* Ub = DU + mbase;
    float* Ob = O + qkvbase;

    // ---- Load Q tile, folding in the 1/sqrt(64) scale ----
    for (int i = t; i < BQ * (Dc / 4); i += NTHREADS) {
        int q = i >> 4, d4 = i & 15;
        float4 v = ((const float4*)(Qb + (size_t)(q0 + q) * Dc))[d4];
        v.x *= 0.125f; v.y *= 0.125f; v.z *= 0.125f; v.w *= 0.125f;
        ((float4*)(sQ + q * DPAD))[d4] = v;
    }
    if (t < BQ) { sMx[t] = -INFINITY; sZ[t] = 0.f; }

    const int lane = t & 31;
    const int w    = t >> 5;                 // 8 warps

    // Phase-D mapping: warp w owns q rows [16w, 16w+16); lane owns 8 rows
    // (upper/lower half by lane>>4) x one float4 d-chunk (lane&15).
    const int qb = (w << 4) + ((lane >> 4) << 3);
    const int dc = lane & 15;
    float4 acc[8];
    #pragma unroll
    for (int i = 0; i < 8; i++) acc[i] = make_float4(0.f, 0.f, 0.f, 0.f);

    // Phase-A mapping: 8x4 micro-tile; q rows tq..tq+7, k cols 4u..4u+3
    // (contiguous -> float4 tw/du/mask loads). Row reductions span the
    // 16-lane group u=0..15, which lies within one warp half.
    const int tq = (t >> 4) << 3;            // 0,8,...,120
    const int u  = t & 15;

    __syncthreads();

    for (int kt = 0; kt < Sc / BKT; kt++) {
        const int k0 = kt * BKT;

        // ---- Load K,V tiles ----
        for (int i = t; i < BKT * (Dc / 4); i += NTHREADS) {
            int k = i >> 4, d4 = i & 15;
            ((float4*)(sK + k * DPAD))[d4] =
                ((const float4*)(Kb + (size_t)(k0 + k) * Dc))[d4];
            ((float4*)(sV + k * DPAD))[d4] =
                ((const float4*)(Vb + (size_t)(k0 + k) * Dc))[d4];
        }
        __syncthreads();

        // ---- Fused Phase A: S = Q K^T, mask, online softmax, tw*drop, sP ----
        {
            float s[8][4];
            #pragma unroll
            for (int i = 0; i < 8; i++)
                #pragma unroll
                for (int j = 0; j < 4; j++) s[i][j] = 0.f;

            #pragma unroll 2
            for (int d4 = 0; d4 < 16; d4++) {
                float4 kv0 = ((const float4*)(sK + (4*u + 0) * DPAD))[d4];
                float4 kv1 = ((const float4*)(sK + (4*u + 1) * DPAD))[d4];
                float4 kv2 = ((const float4*)(sK + (4*u + 2) * DPAD))[d4];
                float4 kv3 = ((const float4*)(sK + (4*u + 3) * DPAD))[d4];
                #pragma unroll
                for (int i = 0; i < 8; i++) {
                    float4 qv = ((const float4*)(sQ + (tq + i) * DPAD))[d4];
                    s[i][0] += qv.x*kv0.x + qv.y*kv0.y + qv.z*kv0.z + qv.w*kv0.w;
                    s[i][1] += qv.x*kv1.x + qv.y*kv1.y + qv.z*kv1.z + qv.w*kv1.w;
                    s[i][2] += qv.x*kv2.x + qv.y*kv2.y + qv.z*kv2.z + qv.w*kv2.w;
                    s[i][3] += qv.x*kv3.x + qv.y*kv3.y + qv.z*kv3.z + qv.w*kv3.w;
                }
            }

            // Apply mask (vector loads; Q was pre-scaled so s is final score)
            if (mask_bytes == 0) {
                #pragma unroll
                for (int i = 0; i < 8; i++) {
                    const size_t roff = (size_t)(q0 + tq + i) * Sc + k0 + 4*u;
                    uint4 mw = *(const uint4*)(MbW + roff);
                    if (mw.x) s[i][0] = -1e9f;
                    if (mw.y) s[i][1] = -1e9f;
                    if (mw.z) s[i][2] = -1e9f;
                    if (mw.w) s[i][3] = -1e9f;
                }
            } else {
                #pragma unroll
                for (int i = 0; i < 8; i++) {
                    const size_t roff = (size_t)(q0 + tq + i) * Sc + k0 + 4*u;
                    uchar4 mb = *(const uchar4*)(MbB + roff);
                    if (mb.x) s[i][0] = -1e9f;
                    if (mb.y) s[i][1] = -1e9f;
                    if (mb.z) s[i][2] = -1e9f;
                    if (mb.w) s[i][3] = -1e9f;
                }
            }

            // Per-row: max-reduce, exp, sum-reduce, fold tw*dropout, store P
            #pragma unroll
            for (int i = 0; i < 8; i++) {
                const int r = tq + i;
                const size_t roff = (size_t)(q0 + r) * Sc + k0 + 4*u;

                float mx = fmaxf(fmaxf(s[i][0], s[i][1]), fmaxf(s[i][2], s[i][3]));
                mx = fmaxf(mx, __shfl_xor_sync(0xffffffffu, mx, 1));
                mx = fmaxf(mx, __shfl_xor_sync(0xffffffffu, mx, 2));
                mx = fmaxf(mx, __shfl_xor_sync(0xffffffffu, mx, 4));
                mx = fmaxf(mx, __shfl_xor_sync(0xffffffffu, mx, 8));

                float mold = sMx[r];
                float mnew = fmaxf(mold, mx);

                float4 tw = *(const float4*)(Tb + roff);
                float4 du = *(const float4*)(Ub + roff);

                float p0 = __expf(s[i][0] - mnew);
                float p1 = __expf(s[i][1] - mnew);
                float p2 = __expf(s[i][2] - mnew);
                float p3 = __expf(s[i][3] - mnew);
                float sum = (p0 + p1) + (p2 + p3);
                sum += __shfl_xor_sync(0xffffffffu, sum, 1);
                sum += __shfl_xor_sync(0xffffffffu, sum, 2);
                sum += __shfl_xor_sync(0xffffffffu, sum, 4);
                sum += __shfl_xor_sync(0xffffffffu, sum, 8);

                float4 pw;
                pw.x = p0 * tw.x * ((du.x >= 0.5f) ? 2.0f : 0.0f);
                pw.y = p1 * tw.y * ((du.y >= 0.5f) ? 2.0f : 0.0f);
                pw.z = p2 * tw.z * ((du.z >= 0.5f) ? 2.0f : 0.0f);
                pw.w = p3 * tw.w * ((du.w >= 0.5f) ? 2.0f : 0.0f);
                ((float4*)(sP + r * BKPAD))[u] = pw;

                if (u == 0) {
                    float c = __expf(mold - mnew);   // 0 on first tile
                    sMx[r] = mnew;
                    sC[r]  = c;
                    sZ[r]  = sZ[r] * c + sum;
                }
            }
        }
        __syncthreads();

        // ---- Phase D: acc = acc*c + P @ V (8 q-rows x 1 chunk per lane) ----
        {
            #pragma unroll
            for (int i = 0; i < 8; i++) {
                float c = sC[qb + i];
                acc[i].x *= c; acc[i].y *= c; acc[i].z *= c; acc[i].w *= c;
            }
            #pragma unroll 2
            for (int k4 = 0; k4 < BKT / 4; k4++) {
                float4 v0 = ((const float4*)(sV + (4*k4 + 0) * DPAD))[dc];
                float4 v1 = ((const float4*)(sV + (4*k4 + 1) * DPAD))[dc];
                float4 v2 = ((const float4*)(sV + (4*k4 + 2) * DPAD))[dc];
                float4 v3 = ((const float4*)(sV + (4*k4 + 3) * DPAD))[dc];
                #pragma unroll
                for (int i = 0; i < 8; i++) {
                    float4 p = ((const float4*)(sP + (qb + i) * BKPAD))[k4];
                    acc[i].x += p.x*v0.x + p.y*v1.x + p.z*v2.x + p.w*v3.x;
                    acc[i].y += p.x*v0.y + p.y*v1.y + p.z*v2.y + p.w*v3.y;
                    acc[i].z += p.x*v0.z + p.y*v1.z + p.z*v2.z + p.w*v3.z;
                    acc[i].w += p.x*v0.w + p.y*v1.w + p.z*v2.w + p.w*v3.w;
                }
            }
        }
        __syncthreads();
    }

    // ---- Epilogue: out = acc / Z ----
    #pragma unroll
    for (int i = 0; i < 8; i++) {
        float inv = 1.0f / sZ[qb + i];
        float4 o = acc[i];
        o.x *= inv; o.y *= inv; o.z *= inv; o.w *= inv;
        ((float4*)(Ob + (size_t)(q0 + qb + i) * Dc))[dc] = o;
    }
}

extern "C" void kernel_launch(void* const* d_in, const int* in_sizes, int n_in,
                              void* d_out, int out_size) {
    const float* Q  = (const float*)d_in[0];
    const float* K  = (const float*)d_in[1];
    const float* V  = (const float*)d_in[2];
    const void*  M  = d_in[3];               // bool mask — dtype detected on device
    const float* TW = (const float*)d_in[4];
    const float* DU = (const float*)d_in[5];
    float* O = (float*)d_out;

    const size_t smem_bytes =
        (size_t)(BQ * DPAD + 2 * BKT * DPAD + BQ * BKPAD + 3 * BQ) * sizeof(float);

    cudaFuncSetAttribute(attn_flash_kernel,
                         cudaFuncAttributeMaxDynamicSharedMemorySize,
                         (int)smem_bytes);

    // 1) Detect mask storage layout (word-bool vs byte-bool).
    detect_mask_dtype_kernel<<<1, 256>>>((const unsigned int*)M);

    // 2) Flash attention, one CTA per (b, h, 128-row q-tile); 2 CTAs/SM.
    dim3 grid(Bc * Hc * (Sc / BQ));   // 512 blocks
    attn_flash_kernel<<<grid, NTHREADS, smem_bytes>>>(Q, K, V, M, TW, DU, O);
}

// round 15
// speedup vs baseline: 2.0205x; 2.0205x over previous
#include <cuda_runtime.h>
#include <math.h>

// Shapes (fixed by the problem)
#define Bc 4
#define Hc 16
#define Sc 1024
#define Dc 64

// Tiling
#define BQ 128          // q rows per CTA (8 warps x 16)
#define BKT 64          // key cols per tile
#define KSTR 68         // sK row stride (words): S-GEMM B-frag LDS conflict-free
#define VSTR 72         // sV row stride (words): PV-GEMM B-frag LDS conflict-free
#define PSTR 68         // per-warp sP row stride
#define NTHREADS 256

// Mask layout flag: 0 = 32-bit words (int32 or float32 bool), 1 = 1-byte bools
__device__ int g_mask_byte_mode;

__global__ void detect_mask_dtype_kernel(const unsigned int* __restrict__ m) {
    __shared__ int bad;
    if (threadIdx.x == 0) bad = 0;
    __syncthreads();
    // int32 bools  -> words in {0,1};  float32 bools -> {0, 0x3F800000}
    // u8 bools     -> packed words like 0x01010101 appear w.p. 7/8 per word
    int local_bad = 0;
    for (int i = threadIdx.x; i < 8192; i += blockDim.x) {
        unsigned int w = m[i];
        if (w != 0u && w != 1u && w != 0x3F800000u) local_bad = 1;
    }
    if (local_bad) bad = 1;
    __syncthreads();
    if (threadIdx.x == 0) g_mask_byte_mode = bad;
}

__device__ __forceinline__ unsigned int f2tf32(float f) {
    unsigned int u;
    asm("cvt.rna.tf32.f32 %0, %1;" : "=r"(u) : "f"(f));
    return u;
}

__device__ __forceinline__ void mma_tf32(float& c0, float& c1, float& c2, float& c3,
                                         unsigned a0, unsigned a1, unsigned a2, unsigned a3,
                                         unsigned b0, unsigned b1) {
    asm("mma.sync.aligned.m16n8k8.row.col.f32.tf32.tf32.f32 "
        "{%0,%1,%2,%3}, {%4,%5,%6,%7}, {%8,%9}, {%0,%1,%2,%3};"
        : "+f"(c0), "+f"(c1), "+f"(c2), "+f"(c3)
        : "r"(a0), "r"(a1), "r"(a2), "r"(a3), "r"(b0), "r"(b1));
}

__global__ __launch_bounds__(NTHREADS, 2)
void attn_mma_kernel(const float* __restrict__ Q,
                     const float* __restrict__ K,
                     const float* __restrict__ V,
                     const void* __restrict__ MSK,
                     const float* __restrict__ TW,
                     const float* __restrict__ DU,
                     float* __restrict__ O) {
    extern __shared__ unsigned int smu[];
    unsigned int* sK = smu;                              // BKT x KSTR (tf32 bits)
    unsigned int* sV = sK + BKT * KSTR;                  // BKT x VSTR (tf32 bits)
    unsigned int* sPall = sV + BKT * VSTR;               // 8 warps x 16 x PSTR

    const int t    = threadIdx.x;
    const int lane = t & 31;
    const int w    = t >> 5;                             // 8 warps
    const int g    = lane >> 2;                          // groupID 0..7
    const int tq   = lane & 3;                           // thread-in-quad 0..3
    unsigned int* sP = sPall + w * 16 * PSTR;            // per-warp P buffer

    const int bh = blockIdx.x >> 3;                      // Sc/BQ == 8 q-tiles
    const int q0 = (blockIdx.x & 7) * BQ;
    const int mask_bytes = g_mask_byte_mode;

    const size_t qkvbase = (size_t)bh * Sc * Dc;
    const size_t mbase   = (size_t)bh * Sc * Sc;
    const float* Qb = Q + qkvbase;
    const float* Kb = K + qkvbase;
    const float* Vb = V + qkvbase;
    const unsigned int*  MbW = (const unsigned int*)MSK + mbase;
    const unsigned char* MbB = (const unsigned char*)MSK + mbase;
    const float* Tb = TW + mbase;
    const float* Ub = DU + mbase;
    float* Ob = O + qkvbase;

    // Global q row for the h=0 half of this thread's fragments (h=1 -> +8)
    const int r0 = q0 + w * 16 + g;

    // ---- Q fragments (tf32, pre-scaled by 1/8), loaded ONCE ----
    unsigned int qa[8][4];
    #pragma unroll
    for (int ks = 0; ks < 8; ks++) {
        const float* Qr0 = Qb + (size_t)r0 * Dc + 8 * ks + tq;
        const float* Qr1 = Qr0 + 8 * Dc;
        qa[ks][0] = f2tf32(Qr0[0] * 0.125f);
        qa[ks][1] = f2tf32(Qr1[0] * 0.125f);
        qa[ks][2] = f2tf32(Qr0[4] * 0.125f);
        qa[ks][3] = f2tf32(Qr1[4] * 0.125f);
    }

    // O accumulators: 8 d-tiles x (c0..c3)
    float oc[8][4];
    #pragma unroll
    for (int nt = 0; nt < 8; nt++)
        oc[nt][0] = oc[nt][1] = oc[nt][2] = oc[nt][3] = 0.f;

    float mrun[2] = { -INFINITY, -INFINITY };
    float zrun[2] = { 0.f, 0.f };

    for (int kt = 0; kt < Sc / BKT; kt++) {
        const int k0 = kt * BKT;

        // ---- Cooperative K,V tile load + tf32 convert ----
        for (int i = t; i < BKT * (Dc / 4); i += NTHREADS) {
            int key = i >> 4, d4 = i & 15;
            float4 kv = ((const float4*)(Kb + (size_t)(k0 + key) * Dc))[d4];
            uint4 kb;
            kb.x = f2tf32(kv.x); kb.y = f2tf32(kv.y);
            kb.z = f2tf32(kv.z); kb.w = f2tf32(kv.w);
            *(uint4*)(sK + key * KSTR + 4 * d4) = kb;
            float4 vv = ((const float4*)(Vb + (size_t)(k0 + key) * Dc))[d4];
            uint4 vb;
            vb.x = f2tf32(vv.x); vb.y = f2tf32(vv.y);
            vb.z = f2tf32(vv.z); vb.w = f2tf32(vv.w);
            *(uint4*)(sV + key * VSTR + 4 * d4) = vb;
        }
        __syncthreads();

        // ---- S = Q K^T : 8 key-tiles x 8 d-steps of m16n8k8 ----
        float s[8][4];
        #pragma unroll
        for (int nt = 0; nt < 8; nt++)
            s[nt][0] = s[nt][1] = s[nt][2] = s[nt][3] = 0.f;

        #pragma unroll
        for (int nt = 0; nt < 8; nt++) {
            const unsigned int* kb = sK + (8 * nt + g) * KSTR + tq;  // conflict-free
            #pragma unroll
            for (int ks = 0; ks < 8; ks++) {
                unsigned int b0 = kb[8 * ks];
                unsigned int b1 = kb[8 * ks + 4];
                mma_tf32(s[nt][0], s[nt][1], s[nt][2], s[nt][3],
                         qa[ks][0], qa[ks][1], qa[ks][2], qa[ks][3], b0, b1);
            }
        }

        // ---- Mask (element (row, col) = (r0 + 8h, k0 + 8nt + 2tq + {0,1})) ----
        if (mask_bytes == 0) {
            #pragma unroll
            for (int nt = 0; nt < 8; nt++) {
                const unsigned int* m0 = MbW + (size_t)r0 * Sc + k0 + 8 * nt + 2 * tq;
                uint2 w0 = *(const uint2*)m0;
                uint2 w1 = *(const uint2*)(m0 + 8 * Sc);
                if (w0.x) s[nt][0] = -1e9f;
                if (w0.y) s[nt][1] = -1e9f;
                if (w1.x) s[nt][2] = -1e9f;
                if (w1.y) s[nt][3] = -1e9f;
            }
        } else {
            #pragma unroll
            for (int nt = 0; nt < 8; nt++) {
                const unsigned char* m0 = MbB + (size_t)r0 * Sc + k0 + 8 * nt + 2 * tq;
                uchar2 b0 = *(const uchar2*)m0;
                uchar2 b1 = *(const uchar2*)(m0 + 8 * Sc);
                if (b0.x) s[nt][0] = -1e9f;
                if (b0.y) s[nt][1] = -1e9f;
                if (b1.x) s[nt][2] = -1e9f;
                if (b1.y) s[nt][3] = -1e9f;
            }
        }

        // ---- Online softmax + tw*dropout fold; write P (tf32) to sP ----
        #pragma unroll
        for (int h = 0; h < 2; h++) {
            float mx = -INFINITY;
            #pragma unroll
            for (int nt = 0; nt < 8; nt++)
                mx = fmaxf(mx, fmaxf(s[nt][2 * h], s[nt][2 * h + 1]));
            mx = fmaxf(mx, __shfl_xor_sync(0xffffffffu, mx, 1));
            mx = fmaxf(mx, __shfl_xor_sync(0xffffffffu, mx, 2));

            float mnew = fmaxf(mrun[h], mx);
            float corr = __expf(mrun[h] - mnew);   // 0 on first tile
            mrun[h] = mnew;

            const float* tw0 = Tb + (size_t)(r0 + 8 * h) * Sc + k0 + 2 * tq;
            const float* du0 = Ub + (size_t)(r0 + 8 * h) * Sc + k0 + 2 * tq;
            float sum = 0.f;
            #pragma unroll
            for (int nt = 0; nt < 8; nt++) {
                float p0 = __expf(s[nt][2 * h]     - mnew);
                float p1 = __expf(s[nt][2 * h + 1] - mnew);
                sum += p0 + p1;
                float2 tw = *(const float2*)(tw0 + 8 * nt);
                float2 du = *(const float2*)(du0 + 8 * nt);
                p0 *= tw.x * ((du.x >= 0.5f) ? 2.0f : 0.0f);
                p1 *= tw.y * ((du.y >= 0.5f) ? 2.0f : 0.0f);
                uint2 pp;
                pp.x = f2tf32(p0);
                pp.y = f2tf32(p1);
                *(uint2*)(sP + (g + 8 * h) * PSTR + 8 * nt + 2 * tq) = pp;
            }
            sum += __shfl_xor_sync(0xffffffffu, sum, 1);
            sum += __shfl_xor_sync(0xffffffffu, sum, 2);
            zrun[h] = zrun[h] * corr + sum;

            #pragma unroll
            for (int nt = 0; nt < 8; nt++) {
                oc[nt][2 * h]     *= corr;
                oc[nt][2 * h + 1] *= corr;
            }
        }
        __syncwarp();   // sP written by other lanes of this warp; order before reads

        // ---- O += P V : 8 key-steps x 8 d-tiles of m16n8k8 ----
        #pragma unroll
        for (int ks = 0; ks < 8; ks++) {
            const unsigned int* pb = sP + g * PSTR + 8 * ks + tq;     // conflict-free
            unsigned int a0 = pb[0];
            unsigned int a1 = pb[8 * PSTR];
            unsigned int a2 = pb[4];
            unsigned int a3 = pb[8 * PSTR + 4];
            const unsigned int* vb = sV + (8 * ks + tq) * VSTR + g;   // conflict-free
            #pragma unroll
            for (int nt = 0; nt < 8; nt++) {
                unsigned int b0 = vb[8 * nt];
                unsigned int b1 = vb[4 * VSTR + 8 * nt];
                mma_tf32(oc[nt][0], oc[nt][1], oc[nt][2], oc[nt][3],
                         a0, a1, a2, a3, b0, b1);
            }
        }
        __syncthreads();   // sK/sV reuse next tile
    }

    // ---- Epilogue: out = acc / Z ----
    #pragma unroll
    for (int h = 0; h < 2; h++) {
        float inv = 1.0f / zrun[h];
        float* Or = Ob + (size_t)(r0 + 8 * h) * Dc + 2 * tq;
        #pragma unroll
        for (int nt = 0; nt < 8; nt++) {
            float2 o;
            o.x = oc[nt][2 * h]     * inv;
            o.y = oc[nt][2 * h + 1] * inv;
            *(float2*)(Or + 8 * nt) = o;
        }
    }
}

extern "C" void kernel_launch(void* const* d_in, const int* in_sizes, int n_in,
                              void* d_out, int out_size) {
    const float* Q  = (const float*)d_in[0];
    const float* K  = (const float*)d_in[1];
    const float* V  = (const float*)d_in[2];
    const void*  M  = d_in[3];               // bool mask — dtype detected on device
    const float* TW = (const float*)d_in[4];
    const float* DU = (const float*)d_in[5];
    float* O = (float*)d_out;

    const size_t smem_bytes =
        (size_t)(BKT * KSTR + BKT * VSTR + 8 * 16 * PSTR) * sizeof(unsigned int);

    cudaFuncSetAttribute(attn_mma_kernel,
                         cudaFuncAttributeMaxDynamicSharedMemorySize,
                         (int)smem_bytes);

    // 1) Detect mask storage layout (word-bool vs byte-bool).
    detect_mask_dtype_kernel<<<1, 256>>>((const unsigned int*)M);

    // 2) Tensor-core flash attention, one CTA per (b, h, 128-row q-tile).
    dim3 grid(Bc * Hc * (Sc / BQ));   // 512 blocks
    attn_mma_kernel<<<grid, NTHREADS, smem_bytes>>>(Q, K, V, M, TW, DU, O);
}

// round 16
// speedup vs baseline: 2.0207x; 1.0001x over previous
#include <cuda_runtime.h>
#include <math.h>

// Shapes (fixed by the problem)
#define Bc 4
#define Hc 16
#define Sc 1024
#define Dc 64

// Tiling
#define BQ 128          // q rows per CTA (8 warps x 16)
#define BKT 64          // key cols per tile
#define KSTR 68         // sK row stride (words): S-GEMM B-frag LDS conflict-free
#define VSTR 72         // sV row stride (words): PV-GEMM B-frag LDS conflict-free
#define PSTR 68         // per-warp sP row stride
#define NTHREADS 256

// Mask layout flag: 0 = 32-bit words (int32 or float32 bool), 1 = 1-byte bools
__device__ int g_mask_byte_mode;

__global__ void detect_mask_dtype_kernel(const unsigned int* __restrict__ m) {
    __shared__ int bad;
    if (threadIdx.x == 0) bad = 0;
    __syncthreads();
    // int32 bools  -> words in {0,1};  float32 bools -> {0, 0x3F800000}
    // u8 bools     -> packed words like 0x01010101 appear w.p. 7/8 per word
    int local_bad = 0;
    for (int i = threadIdx.x; i < 8192; i += blockDim.x) {
        unsigned int w = m[i];
        if (w != 0u && w != 1u && w != 0x3F800000u) local_bad = 1;
    }
    if (local_bad) bad = 1;
    __syncthreads();
    if (threadIdx.x == 0) g_mask_byte_mode = bad;
}

__device__ __forceinline__ unsigned int f2tf32(float f) {
    unsigned int u;
    asm("cvt.rna.tf32.f32 %0, %1;" : "=r"(u) : "f"(f));
    return u;
}

__device__ __forceinline__ void mma_tf32(float& c0, float& c1, float& c2, float& c3,
                                         unsigned a0, unsigned a1, unsigned a2, unsigned a3,
                                         unsigned b0, unsigned b1) {
    asm("mma.sync.aligned.m16n8k8.row.col.f32.tf32.tf32.f32 "
        "{%0,%1,%2,%3}, {%4,%5,%6,%7}, {%8,%9}, {%0,%1,%2,%3};"
        : "+f"(c0), "+f"(c1), "+f"(c2), "+f"(c3)
        : "r"(a0), "r"(a1), "r"(a2), "r"(a3), "r"(b0), "r"(b1));
}

__global__ __launch_bounds__(NTHREADS, 2)
void attn_mma_kernel(const float* __restrict__ Q,
                     const float* __restrict__ K,
                     const float* __restrict__ V,
                     const void* __restrict__ MSK,
                     const float* __restrict__ TW,
                     const float* __restrict__ DU,
                     float* __restrict__ O) {
    extern __shared__ unsigned int smu[];
    unsigned int* sK = smu;                              // BKT x KSTR (tf32 bits)
    unsigned int* sV = sK + BKT * KSTR;                  // BKT x VSTR (tf32 bits)
    unsigned int* sPall = sV + BKT * VSTR;               // 8 warps x 16 x PSTR

    const int t    = threadIdx.x;
    const int lane = t & 31;
    const int w    = t >> 5;                             // 8 warps
    const int g    = lane >> 2;                          // groupID 0..7
    const int tq   = lane & 3;                           // thread-in-quad 0..3
    unsigned int* sP = sPall + w * 16 * PSTR;            // per-warp P buffer

    const int bh = blockIdx.x >> 3;                      // Sc/BQ == 8 q-tiles
    const int q0 = (blockIdx.x & 7) * BQ;
    const int mask_bytes = g_mask_byte_mode;

    const size_t qkvbase = (size_t)bh * Sc * Dc;
    const size_t mbase   = (size_t)bh * Sc * Sc;
    const float* Qb = Q + qkvbase;
    const float* Kb = K + qkvbase;
    const float* Vb = V + qkvbase;
    const unsigned int*  MbW = (const unsigned int*)MSK + mbase;
    const unsigned char* MbB = (const unsigned char*)MSK + mbase;
    const float* Tb = TW + mbase;
    const float* Ub = DU + mbase;
    float* Ob = O + qkvbase;

    // Global q row for the h=0 half of this thread's fragments (h=1 -> +8)
    const int r0 = q0 + w * 16 + g;

    // ---- Q fragments (tf32, pre-scaled by 1/8), loaded ONCE ----
    unsigned int qa[8][4];
    #pragma unroll
    for (int ks = 0; ks < 8; ks++) {
        const float* Qr0 = Qb + (size_t)r0 * Dc + 8 * ks + tq;
        const float* Qr1 = Qr0 + 8 * Dc;
        qa[ks][0] = f2tf32(Qr0[0] * 0.125f);
        qa[ks][1] = f2tf32(Qr1[0] * 0.125f);
        qa[ks][2] = f2tf32(Qr0[4] * 0.125f);
        qa[ks][3] = f2tf32(Qr1[4] * 0.125f);
    }

    // O accumulators: 8 d-tiles x (c0..c3)
    float oc[8][4];
    #pragma unroll
    for (int nt = 0; nt < 8; nt++)
        oc[nt][0] = oc[nt][1] = oc[nt][2] = oc[nt][3] = 0.f;

    float mrun[2] = { -INFINITY, -INFINITY };
    float zrun[2] = { 0.f, 0.f };

    for (int kt = 0; kt < Sc / BKT; kt++) {
        const int k0 = kt * BKT;

        // ---- Cooperative K,V tile load + tf32 convert ----
        for (int i = t; i < BKT * (Dc / 4); i += NTHREADS) {
            int key = i >> 4, d4 = i & 15;
            float4 kv = ((const float4*)(Kb + (size_t)(k0 + key) * Dc))[d4];
            uint4 kb;
            kb.x = f2tf32(kv.x); kb.y = f2tf32(kv.y);
            kb.z = f2tf32(kv.z); kb.w = f2tf32(kv.w);
            *(uint4*)(sK + key * KSTR + 4 * d4) = kb;
            float4 vv = ((const float4*)(Vb + (size_t)(k0 + key) * Dc))[d4];
            uint4 vb;
            vb.x = f2tf32(vv.x); vb.y = f2tf32(vv.y);
            vb.z = f2tf32(vv.z); vb.w = f2tf32(vv.w);
            *(uint4*)(sV + key * VSTR + 4 * d4) = vb;
        }
        __syncthreads();

        // ---- S = Q K^T : 8 key-tiles x 8 d-steps of m16n8k8 ----
        float s[8][4];
        #pragma unroll
        for (int nt = 0; nt < 8; nt++)
            s[nt][0] = s[nt][1] = s[nt][2] = s[nt][3] = 0.f;

        #pragma unroll
        for (int nt = 0; nt < 8; nt++) {
            const unsigned int* kb = sK + (8 * nt + g) * KSTR + tq;  // conflict-free
            #pragma unroll
            for (int ks = 0; ks < 8; ks++) {
                unsigned int b0 = kb[8 * ks];
                unsigned int b1 = kb[8 * ks + 4];
                mma_tf32(s[nt][0], s[nt][1], s[nt][2], s[nt][3],
                         qa[ks][0], qa[ks][1], qa[ks][2], qa[ks][3], b0, b1);
            }
        }

        // ---- Mask (element (row, col) = (r0 + 8h, k0 + 8nt + 2tq + {0,1})) ----
        if (mask_bytes == 0) {
            #pragma unroll
            for (int nt = 0; nt < 8; nt++) {
                const unsigned int* m0 = MbW + (size_t)r0 * Sc + k0 + 8 * nt + 2 * tq;
                uint2 w0 = *(const uint2*)m0;
                uint2 w1 = *(const uint2*)(m0 + 8 * Sc);
                if (w0.x) s[nt][0] = -1e9f;
                if (w0.y) s[nt][1] = -1e9f;
                if (w1.x) s[nt][2] = -1e9f;
                if (w1.y) s[nt][3] = -1e9f;
            }
        } else {
            #pragma unroll
            for (int nt = 0; nt < 8; nt++) {
                const unsigned char* m0 = MbB + (size_t)r0 * Sc + k0 + 8 * nt + 2 * tq;
                uchar2 b0 = *(const uchar2*)m0;
                uchar2 b1 = *(const uchar2*)(m0 + 8 * Sc);
                if (b0.x) s[nt][0] = -1e9f;
                if (b0.y) s[nt][1] = -1e9f;
                if (b1.x) s[nt][2] = -1e9f;
                if (b1.y) s[nt][3] = -1e9f;
            }
        }

        // ---- Online softmax + tw*dropout fold; write P (tf32) to sP ----
        #pragma unroll
        for (int h = 0; h < 2; h++) {
            float mx = -INFINITY;
            #pragma unroll
            for (int nt = 0; nt < 8; nt++)
                mx = fmaxf(mx, fmaxf(s[nt][2 * h], s[nt][2 * h + 1]));
            mx = fmaxf(mx, __shfl_xor_sync(0xffffffffu, mx, 1));
            mx = fmaxf(mx, __shfl_xor_sync(0xffffffffu, mx, 2));

            float mnew = fmaxf(mrun[h], mx);
            float corr = __expf(mrun[h] - mnew);   // 0 on first tile
            mrun[h] = mnew;

            const float* tw0 = Tb + (size_t)(r0 + 8 * h) * Sc + k0 + 2 * tq;
            const float* du0 = Ub + (size_t)(r0 + 8 * h) * Sc + k0 + 2 * tq;
            float sum = 0.f;
            #pragma unroll
            for (int nt = 0; nt < 8; nt++) {
                float p0 = __expf(s[nt][2 * h]     - mnew);
                float p1 = __expf(s[nt][2 * h + 1] - mnew);
                sum += p0 + p1;
                float2 tw = *(const float2*)(tw0 + 8 * nt);
                float2 du = *(const float2*)(du0 + 8 * nt);
                p0 *= tw.x * ((du.x >= 0.5f) ? 2.0f : 0.0f);
                p1 *= tw.y * ((du.y >= 0.5f) ? 2.0f : 0.0f);
                uint2 pp;
                pp.x = f2tf32(p0);
                pp.y = f2tf32(p1);
                *(uint2*)(sP + (g + 8 * h) * PSTR + 8 * nt + 2 * tq) = pp;
            }
            sum += __shfl_xor_sync(0xffffffffu, sum, 1);
            sum += __shfl_xor_sync(0xffffffffu, sum, 2);
            zrun[h] = zrun[h] * corr + sum;

            #pragma unroll
            for (int nt = 0; nt < 8; nt++) {
                oc[nt][2 * h]     *= corr;
                oc[nt][2 * h + 1] *= corr;
            }
        }
        __syncwarp();   // sP written by other lanes of this warp; order before reads

        // ---- O += P V : 8 key-steps x 8 d-tiles of m16n8k8 ----
        #pragma unroll
        for (int ks = 0; ks < 8; ks++) {
            const unsigned int* pb = sP + g * PSTR + 8 * ks + tq;     // conflict-free
            unsigned int a0 = pb[0];
            unsigned int a1 = pb[8 * PSTR];
            unsigned int a2 = pb[4];
            unsigned int a3 = pb[8 * PSTR + 4];
            const unsigned int* vb = sV + (8 * ks + tq) * VSTR + g;   // conflict-free
            #pragma unroll
            for (int nt = 0; nt < 8; nt++) {
                unsigned int b0 = vb[8 * nt];
                unsigned int b1 = vb[4 * VSTR + 8 * nt];
                mma_tf32(oc[nt][0], oc[nt][1], oc[nt][2], oc[nt][3],
                         a0, a1, a2, a3, b0, b1);
            }
        }
        __syncthreads();   // sK/sV reuse next tile
    }

    // ---- Epilogue: out = acc / Z ----
    #pragma unroll
    for (int h = 0; h < 2; h++) {
        float inv = 1.0f / zrun[h];
        float* Or = Ob + (size_t)(r0 + 8 * h) * Dc + 2 * tq;
        #pragma unroll
        for (int nt = 0; nt < 8; nt++) {
            float2 o;
            o.x = oc[nt][2 * h]     * inv;
            o.y = oc[nt][2 * h + 1] * inv;
            *(float2*)(Or + 8 * nt) = o;
        }
    }
}

extern "C" void kernel_launch(void* const* d_in, const int* in_sizes, int n_in,
                              void* d_out, int out_size) {
    const float* Q  = (const float*)d_in[0];
    const float* K  = (const float*)d_in[1];
    const float* V  = (const float*)d_in[2];
    const void*  M  = d_in[3];               // bool mask — dtype detected on device
    const float* TW = (const float*)d_in[4];
    const float* DU = (const float*)d_in[5];
    float* O = (float*)d_out;

    const size_t smem_bytes =
        (size_t)(BKT * KSTR + BKT * VSTR + 8 * 16 * PSTR) * sizeof(unsigned int);

    cudaFuncSetAttribute(attn_mma_kernel,
                         cudaFuncAttributeMaxDynamicSharedMemorySize,
                         (int)smem_bytes);

    // 1) Detect mask storage layout (word-bool vs byte-bool).
    detect_mask_dtype_kernel<<<1, 256>>>((const unsigned int*)M);

    // 2) Tensor-core flash attention, one CTA per (b, h, 128-row q-tile).
    dim3 grid(Bc * Hc * (Sc / BQ));   // 512 blocks
    attn_mma_kernel<<<grid, NTHREADS, smem_bytes>>>(Q, K, V, M, TW, DU, O);
}